// round 3
// baseline (speedup 1.0000x reference)
#include <cuda_runtime.h>
#include <cstdint>
#include <cstddef>

// Problem dims (fixed for this dataset entry)
#define CKDIM 64
#define K2    128          // stacked [mk; mk^2]
#define NP    4096         // pixels (H*W)
#define NN    8192         // memory slots (T*H*W)
#define NV    1024         // nobj*cv

// ---------------- scratch (static device memory; no allocs) ----------------
__device__ float g_S[(size_t)NN * NP];   // sim, then exp(sim - max) in place (134 MB)
__device__ float g_A[(size_t)K2 * NN];   // rows 0..63: mk, rows 64..127: mk^2
__device__ float g_Bm[(size_t)K2 * NP];  // rows 0..63: 2*qk*qe, rows 64..127: -qe
__device__ float g_bsq[NP];
__device__ float g_msn[NN];              // ms * (1/sqrt(64)) = ms * 0.125
__device__ float g_rinv[NP];             // 1 / sumexp per pixel

// ---------------- prep kernels ----------------
__global__ void prep_q_kernel(const float* __restrict__ qk, const float* __restrict__ qe) {
    int p = blockIdx.x * blockDim.x + threadIdx.x;
    if (p >= NP) return;
    float bsq = 0.f;
#pragma unroll
    for (int c = 0; c < CKDIM; ++c) {
        float k = qk[c * NP + p];
        float e = qe[c * NP + p];
        g_Bm[(size_t)c * NP + p]           = 2.f * k * e;
        g_Bm[(size_t)(CKDIM + c) * NP + p] = -e;
        bsq = fmaf(e * k, k, bsq);
    }
    g_bsq[p] = bsq;
}

__global__ void prep_m_kernel(const float* __restrict__ mk, const float* __restrict__ ms) {
    int n = blockIdx.x * blockDim.x + threadIdx.x;
    if (n >= NN) return;
#pragma unroll
    for (int c = 0; c < CKDIM; ++c) {
        float v = mk[c * NN + n];
        g_A[(size_t)c * NN + n]           = v;
        g_A[(size_t)(CKDIM + c) * NN + n] = v * v;
    }
    g_msn[n] = ms[n] * 0.125f;
}

// ---------------- sim kernel: S[n][p] = msn[n] * (sum_k A[k][n]*Bm[k][p] - bsq[p]) ----
// fp32 SIMT tiled GEMM, 128x128 block tile, K=128, 8x8 per thread.
__global__ __launch_bounds__(256) void sim_kernel() {
    __shared__ float sA[16][128];
    __shared__ float sB[16][128];
    const int p0 = blockIdx.x * 128;
    const int n0 = blockIdx.y * 128;
    const int tid = threadIdx.x;
    const int tx = tid & 15;   // p sub-tile
    const int ty = tid >> 4;   // n sub-tile

    float acc[8][8];
#pragma unroll
    for (int i = 0; i < 8; ++i)
#pragma unroll
        for (int j = 0; j < 8; ++j) acc[i][j] = 0.f;

    for (int kt = 0; kt < K2 / 16; ++kt) {
#pragma unroll
        for (int s = 0; s < 2; ++s) {
            int id = tid + s * 256;          // 0..511
            int r  = id >> 5;                // 0..15
            int c4 = (id & 31) << 2;         // 0..124
            *(float4*)&sA[r][c4] = *(const float4*)&g_A[(size_t)(kt * 16 + r) * NN + n0 + c4];
            *(float4*)&sB[r][c4] = *(const float4*)&g_Bm[(size_t)(kt * 16 + r) * NP + p0 + c4];
        }
        __syncthreads();
#pragma unroll
        for (int kk = 0; kk < 16; ++kk) {
            float a[8], b[8];
            *(float4*)&a[0] = *(float4*)&sA[kk][ty * 8];
            *(float4*)&a[4] = *(float4*)&sA[kk][ty * 8 + 4];
            *(float4*)&b[0] = *(float4*)&sB[kk][tx * 8];
            *(float4*)&b[4] = *(float4*)&sB[kk][tx * 8 + 4];
#pragma unroll
            for (int i = 0; i < 8; ++i)
#pragma unroll
                for (int j = 0; j < 8; ++j)
                    acc[i][j] = fmaf(a[i], b[j], acc[i][j]);
        }
        __syncthreads();
    }

    float msnv[8], bsqv[8];
#pragma unroll
    for (int i = 0; i < 8; ++i) msnv[i] = g_msn[n0 + ty * 8 + i];
#pragma unroll
    for (int j = 0; j < 8; ++j) bsqv[j] = g_bsq[p0 + tx * 8 + j];

#pragma unroll
    for (int i = 0; i < 8; ++i) {
        int n = n0 + ty * 8 + i;
        float4 o0, o1;
        o0.x = msnv[i] * (acc[i][0] - bsqv[0]);
        o0.y = msnv[i] * (acc[i][1] - bsqv[1]);
        o0.z = msnv[i] * (acc[i][2] - bsqv[2]);
        o0.w = msnv[i] * (acc[i][3] - bsqv[3]);
        o1.x = msnv[i] * (acc[i][4] - bsqv[4]);
        o1.y = msnv[i] * (acc[i][5] - bsqv[5]);
        o1.z = msnv[i] * (acc[i][6] - bsqv[6]);
        o1.w = msnv[i] * (acc[i][7] - bsqv[7]);
        *(float4*)&g_S[(size_t)n * NP + p0 + tx * 8]     = o0;
        *(float4*)&g_S[(size_t)n * NP + p0 + tx * 8 + 4] = o1;
    }
}

// ---------------- softmax over n (columns of S), in place; rinv saved -------------
// block = (32 pixels) x (8 n-strides), 128 blocks; coalesced 128B rows.
__global__ __launch_bounds__(256) void softmax_kernel() {
    __shared__ float red[8][33];
    __shared__ float bc[32];
    const int tx = threadIdx.x;   // 0..31 pixel
    const int ty = threadIdx.y;   // 0..7  n-stride
    const int p = blockIdx.x * 32 + tx;

    float m = -3.0e38f;
#pragma unroll 8
    for (int n = ty; n < NN; n += 8)
        m = fmaxf(m, g_S[(size_t)n * NP + p]);
    red[ty][tx] = m;
    __syncthreads();
    if (ty == 0) {
#pragma unroll
        for (int y = 1; y < 8; ++y) m = fmaxf(m, red[y][tx]);
        bc[tx] = m;
    }
    __syncthreads();
    m = bc[tx];

    float s = 0.f;
#pragma unroll 8
    for (int n = ty; n < NN; n += 8) {
        size_t idx = (size_t)n * NP + p;
        float e = __expf(g_S[idx] - m);
        g_S[idx] = e;
        s += e;
    }
    red[ty][tx] = s;
    __syncthreads();
    if (ty == 0) {
#pragma unroll
        for (int y = 1; y < 8; ++y) s += red[y][tx];
        g_rinv[p] = 1.0f / s;
    }
}

// ---------------- readout GEMM: out[v][p] = rinv[p] * sum_n mv[v][n] * E[n][p] -----
// tf32 mma.sync m16n8k8, BM=BN=128, BK=16, cp.async double-buffered.
#define CBM 128
#define CBN 128
#define CBK 16
#define CKT (NN / CBK)   // 512

__device__ __forceinline__ uint32_t f2tf32(float f) {
    uint32_t r;
    asm("cvt.rna.tf32.f32 %0, %1;" : "=r"(r) : "f"(f));
    return r;
}
__device__ __forceinline__ void cp16(uint32_t dst, const float* src) {
    asm volatile("cp.async.cg.shared.global [%0], [%1], 16;\n" :: "r"(dst), "l"(src));
}

__global__ __launch_bounds__(256) void out_gemm_kernel(const float* __restrict__ mv,
                                                       float* __restrict__ out) {
    __shared__ float As[2][CBM][20];    // [m][k], stride 20 -> conflict-free frag loads
    __shared__ float Bs[2][CBK][136];   // [k][p], stride 136 -> conflict-free frag loads
    const int tid  = threadIdx.x;
    const int bN   = blockIdx.x * CBN;  // pixel offset
    const int bM   = blockIdx.y * CBM;  // value-dim offset
    const int warp = tid >> 5;
    const int lane = tid & 31;
    const int wm = (warp & 3) * 32;     // 4 warps along M -> WM=32
    const int wn = (warp >> 2) * 64;    // 2 warps along N -> WN=64
    const int g  = lane >> 2;           // groupID
    const int tg = lane & 3;            // thread in group

    float acc[2][8][4];
#pragma unroll
    for (int i = 0; i < 2; ++i)
#pragma unroll
        for (int j = 0; j < 8; ++j)
#pragma unroll
            for (int r = 0; r < 4; ++r) acc[i][j][r] = 0.f;

    // ---- tile loader (A: 128x16 from mv; B: 16x128 from g_S) ----
    auto load_tiles = [&](int kt, int stage) {
#pragma unroll
        for (int s = 0; s < 2; ++s) {
            int id = tid + s * 256;          // 0..511
            int r  = id >> 2;                // 0..127
            int c4 = (id & 3) << 2;          // 0,4,8,12
            const float* src = &mv[(size_t)(bM + r) * NN + kt * CBK + c4];
            cp16((uint32_t)__cvta_generic_to_shared(&As[stage][r][c4]), src);
        }
#pragma unroll
        for (int s = 0; s < 2; ++s) {
            int id = tid + s * 256;
            int r  = id >> 5;                // 0..15
            int c4 = (id & 31) << 2;         // 0..124
            const float* src = &g_S[(size_t)(kt * CBK + r) * NP + bN + c4];
            cp16((uint32_t)__cvta_generic_to_shared(&Bs[stage][r][c4]), src);
        }
    };

    load_tiles(0, 0);
    asm volatile("cp.async.commit_group;\n" ::);

    for (int kt = 0; kt < CKT; ++kt) {
        const int cur = kt & 1;
        if (kt + 1 < CKT) {
            load_tiles(kt + 1, cur ^ 1);
            asm volatile("cp.async.commit_group;\n" ::);
            asm volatile("cp.async.wait_group 1;\n" ::);
        } else {
            asm volatile("cp.async.wait_group 0;\n" ::);
        }
        __syncthreads();

#pragma unroll
        for (int ks = 0; ks < 2; ++ks) {
            const int k0 = ks * 8;
            uint32_t af[2][4];
#pragma unroll
            for (int i = 0; i < 2; ++i) {
                int mrow = wm + 16 * i;
                af[i][0] = f2tf32(As[cur][mrow + g][k0 + tg]);
                af[i][1] = f2tf32(As[cur][mrow + g + 8][k0 + tg]);
                af[i][2] = f2tf32(As[cur][mrow + g][k0 + tg + 4]);
                af[i][3] = f2tf32(As[cur][mrow + g + 8][k0 + tg + 4]);
            }
            uint32_t bf[8][2];
#pragma unroll
            for (int j = 0; j < 8; ++j) {
                int ncol = wn + 8 * j + g;
                bf[j][0] = f2tf32(Bs[cur][k0 + tg][ncol]);
                bf[j][1] = f2tf32(Bs[cur][k0 + tg + 4][ncol]);
            }
#pragma unroll
            for (int i = 0; i < 2; ++i)
#pragma unroll
                for (int j = 0; j < 8; ++j) {
                    asm volatile(
                        "mma.sync.aligned.m16n8k8.row.col.f32.tf32.tf32.f32 "
                        "{%0,%1,%2,%3}, {%4,%5,%6,%7}, {%8,%9}, {%0,%1,%2,%3};\n"
                        : "+f"(acc[i][j][0]), "+f"(acc[i][j][1]),
                          "+f"(acc[i][j][2]), "+f"(acc[i][j][3])
                        : "r"(af[i][0]), "r"(af[i][1]), "r"(af[i][2]), "r"(af[i][3]),
                          "r"(bf[j][0]), "r"(bf[j][1]));
                }
        }
        __syncthreads();
    }

    // epilogue: scale by rinv[p], write fp32
#pragma unroll
    for (int j = 0; j < 8; ++j) {
        int c = bN + wn + 8 * j + 2 * tg;
        float r0 = g_rinv[c];
        float r1 = g_rinv[c + 1];
#pragma unroll
        for (int i = 0; i < 2; ++i) {
            int rrow = bM + wm + 16 * i + g;
            out[(size_t)rrow * NP + c]           = acc[i][j][0] * r0;
            out[(size_t)rrow * NP + c + 1]       = acc[i][j][1] * r1;
            out[(size_t)(rrow + 8) * NP + c]     = acc[i][j][2] * r0;
            out[(size_t)(rrow + 8) * NP + c + 1] = acc[i][j][3] * r1;
        }
    }
}

// ---------------- launch ----------------
extern "C" void kernel_launch(void* const* d_in, const int* in_sizes, int n_in,
                              void* d_out, int out_size) {
    const float* qk = (const float*)d_in[0];  // query_key       (64, 4096)
    const float* qe = (const float*)d_in[1];  // query_selection (64, 4096)
    const float* mk = (const float*)d_in[2];  // memory_key      (64, 8192)
    const float* ms = (const float*)d_in[3];  // memory_shrinkage(8192)
    const float* mv = (const float*)d_in[4];  // memory_value    (1024, 8192)
    float* out = (float*)d_out;               // (1024, 4096)

    prep_q_kernel<<<NP / 256, 256>>>(qk, qe);
    prep_m_kernel<<<NN / 256, 256>>>(mk, ms);
    sim_kernel<<<dim3(NP / 128, NN / 128), 256>>>();
    softmax_kernel<<<NP / 32, dim3(32, 8)>>>();
    out_gemm_kernel<<<dim3(NP / CBN, NV / CBM), 256>>>(mv, out);
}

// round 4
// speedup vs baseline: 1.3507x; 1.3507x over previous
#include <cuda_runtime.h>
#include <cstdint>
#include <cstddef>

#define CKDIM 64
#define K2    128          // stacked [mk; mk^2]
#define NP    4096         // pixels (H*W)
#define NN    8192         // memory slots (T*H*W)
#define NV    1024         // nobj*cv
#define NBLK  (NN / 128)   // 64 n-tiles

// ---------------- scratch (static device memory; no allocs) ----------------
__device__ float g_S[(size_t)NN * NP];     // exp(sim), tf32-rounded (134 MB)
__device__ float g_Ahi[(size_t)NN * K2];   // [n][k] hi split of [mk; mk^2]
__device__ float g_Alo[(size_t)NN * K2];   // [n][k] lo split
__device__ float g_Bhi[(size_t)K2 * NP];   // [k][p] hi split of [2qk*qe; -qe]
__device__ float g_Blo[(size_t)K2 * NP];   // [k][p] lo split
__device__ float g_MV[(size_t)NV * NN];    // tf32-rounded mv
__device__ float g_bsq[NP];
__device__ float g_msn[NN];                // ms / sqrt(64)
__device__ float g_part[(size_t)NBLK * NP];// per-n-tile column partial sums
__device__ float g_rinv[NP];

__device__ __forceinline__ float tf32r(float x) {
    uint32_t u;
    asm("cvt.rna.tf32.f32 %0, %1;" : "=r"(u) : "f"(x));
    return __uint_as_float(u);
}
__device__ __forceinline__ void cp16(uint32_t dst, const float* src) {
    asm volatile("cp.async.cg.shared.global [%0], [%1], 16;\n" :: "r"(dst), "l"(src));
}
#define MMA_TF32(acc, a, b)                                                          \
    asm volatile(                                                                    \
        "mma.sync.aligned.m16n8k8.row.col.f32.tf32.tf32.f32 "                        \
        "{%0,%1,%2,%3}, {%4,%5,%6,%7}, {%8,%9}, {%0,%1,%2,%3};\n"                    \
        : "+f"((acc)[0]), "+f"((acc)[1]), "+f"((acc)[2]), "+f"((acc)[3])             \
        : "r"(__float_as_uint((a)[0])), "r"(__float_as_uint((a)[1])),                \
          "r"(__float_as_uint((a)[2])), "r"(__float_as_uint((a)[3])),                \
          "r"(__float_as_uint((b)[0])), "r"(__float_as_uint((b)[1])))

// ---------------- prep kernels ----------------
__global__ void prep_q_kernel(const float* __restrict__ qk, const float* __restrict__ qe) {
    int p = blockIdx.x * blockDim.x + threadIdx.x;
    if (p >= NP) return;
    float bsq = 0.f;
#pragma unroll
    for (int c = 0; c < CKDIM; ++c) {
        float k = qk[c * NP + p];
        float e = qe[c * NP + p];
        float b1 = 2.f * k * e;
        float b2 = -e;
        float h1 = tf32r(b1), h2 = tf32r(b2);
        g_Bhi[(size_t)c * NP + p]           = h1;
        g_Blo[(size_t)c * NP + p]           = tf32r(b1 - h1);
        g_Bhi[(size_t)(CKDIM + c) * NP + p] = h2;
        g_Blo[(size_t)(CKDIM + c) * NP + p] = tf32r(b2 - h2);
        bsq = fmaf(e * k, k, bsq);
    }
    g_bsq[p] = bsq;
}

__global__ void prep_m_kernel(const float* __restrict__ mk, const float* __restrict__ ms) {
    int n = blockIdx.x * blockDim.x + threadIdx.x;
    if (n >= NN) return;
#pragma unroll
    for (int c = 0; c < CKDIM; ++c) {
        float v = mk[c * NN + n];
        float v2 = v * v;
        float h = tf32r(v), h2 = tf32r(v2);
        g_Ahi[(size_t)n * K2 + c]         = h;
        g_Alo[(size_t)n * K2 + c]         = tf32r(v - h);
        g_Ahi[(size_t)n * K2 + CKDIM + c] = h2;
        g_Alo[(size_t)n * K2 + CKDIM + c] = tf32r(v2 - h2);
    }
    g_msn[n] = ms[n] * 0.125f;
}

__global__ void prep_mv_kernel(const float* __restrict__ mv) {
    size_t i = (size_t)blockIdx.x * blockDim.x + threadIdx.x;  // float4 index
    float4 v = ((const float4*)mv)[i];
    v.x = tf32r(v.x); v.y = tf32r(v.y); v.z = tf32r(v.z); v.w = tf32r(v.w);
    ((float4*)g_MV)[i] = v;
}

// ---------------- sim kernel: split-tf32 MMA + exp + column partial sums ----------
// M=n (128/tile), N=p (128/tile), K=128 in 8 steps of 16, double-buffered cp.async.
__global__ __launch_bounds__(256) void sim_kernel() {
    extern __shared__ float sm[];
    float* Ahi = sm;                 // [2][128][20]
    float* Alo = Ahi + 2 * 128 * 20;
    float* Bhi = Alo + 2 * 128 * 20; // [2][16][136]
    float* Blo = Bhi + 2 * 16 * 136;
    __shared__ float colpart[4][128];

#define SAH(s, r, c) Ahi[(s) * 2560 + (r) * 20 + (c)]
#define SAL(s, r, c) Alo[(s) * 2560 + (r) * 20 + (c)]
#define SBH(s, r, c) Bhi[(s) * 2176 + (r) * 136 + (c)]
#define SBL(s, r, c) Blo[(s) * 2176 + (r) * 136 + (c)]

    const int tid  = threadIdx.x;
    const int bM   = blockIdx.x * 128;  // n offset
    const int bN   = blockIdx.y * 128;  // pixel offset
    const int warp = tid >> 5;
    const int lane = tid & 31;
    const int mw = warp & 3;
    const int wm = mw * 32;
    const int wn = (warp >> 2) * 64;
    const int g  = lane >> 2;
    const int tg = lane & 3;

    float acc[2][8][4];
#pragma unroll
    for (int i = 0; i < 2; ++i)
#pragma unroll
        for (int j = 0; j < 8; ++j)
#pragma unroll
            for (int r = 0; r < 4; ++r) acc[i][j][r] = 0.f;

    auto load_tiles = [&](int kt, int st) {
#pragma unroll
        for (int s = 0; s < 2; ++s) {
            int id = tid + s * 256;       // 0..511
            int r  = id >> 2;             // 0..127
            int c4 = (id & 3) << 2;       // 0,4,8,12
            size_t go = (size_t)(bM + r) * K2 + kt * 16 + c4;
            cp16((uint32_t)__cvta_generic_to_shared(&SAH(st, r, c4)), &g_Ahi[go]);
            cp16((uint32_t)__cvta_generic_to_shared(&SAL(st, r, c4)), &g_Alo[go]);
        }
#pragma unroll
        for (int s = 0; s < 2; ++s) {
            int id = tid + s * 256;
            int r  = id >> 5;             // 0..15
            int c4 = (id & 31) << 2;      // 0..124
            size_t go = (size_t)(kt * 16 + r) * NP + bN + c4;
            cp16((uint32_t)__cvta_generic_to_shared(&SBH(st, r, c4)), &g_Bhi[go]);
            cp16((uint32_t)__cvta_generic_to_shared(&SBL(st, r, c4)), &g_Blo[go]);
        }
    };

    load_tiles(0, 0);
    asm volatile("cp.async.commit_group;\n" ::);

    for (int kt = 0; kt < K2 / 16; ++kt) {
        const int cur = kt & 1;
        if (kt + 1 < K2 / 16) {
            load_tiles(kt + 1, cur ^ 1);
            asm volatile("cp.async.commit_group;\n" ::);
            asm volatile("cp.async.wait_group 1;\n" ::);
        } else {
            asm volatile("cp.async.wait_group 0;\n" ::);
        }
        __syncthreads();

#pragma unroll
        for (int ks = 0; ks < 2; ++ks) {
            const int k0 = ks * 8;
            float ah[2][4], al[2][4], bh[8][2], bl[8][2];
#pragma unroll
            for (int i = 0; i < 2; ++i) {
                int mr = wm + 16 * i;
                ah[i][0] = SAH(cur, mr + g, k0 + tg);
                ah[i][1] = SAH(cur, mr + g + 8, k0 + tg);
                ah[i][2] = SAH(cur, mr + g, k0 + tg + 4);
                ah[i][3] = SAH(cur, mr + g + 8, k0 + tg + 4);
                al[i][0] = SAL(cur, mr + g, k0 + tg);
                al[i][1] = SAL(cur, mr + g + 8, k0 + tg);
                al[i][2] = SAL(cur, mr + g, k0 + tg + 4);
                al[i][3] = SAL(cur, mr + g + 8, k0 + tg + 4);
            }
#pragma unroll
            for (int j = 0; j < 8; ++j) {
                int nc = wn + 8 * j + g;
                bh[j][0] = SBH(cur, k0 + tg, nc);
                bh[j][1] = SBH(cur, k0 + tg + 4, nc);
                bl[j][0] = SBL(cur, k0 + tg, nc);
                bl[j][1] = SBL(cur, k0 + tg + 4, nc);
            }
#pragma unroll
            for (int i = 0; i < 2; ++i)
#pragma unroll
                for (int j = 0; j < 8; ++j) {
                    MMA_TF32(acc[i][j], ah[i], bh[j]);
                    MMA_TF32(acc[i][j], al[i], bh[j]);
                    MMA_TF32(acc[i][j], ah[i], bl[j]);
                }
        }
        __syncthreads();
    }

    // ---- epilogue: exp(msn*(acc - bsq)), write tf32-rounded E, column sums ----
    float bsqv[8][2];
#pragma unroll
    for (int j = 0; j < 8; ++j) {
        int c0 = bN + wn + 8 * j + 2 * tg;
        bsqv[j][0] = g_bsq[c0];
        bsqv[j][1] = g_bsq[c0 + 1];
    }
    float csum[8][2];
#pragma unroll
    for (int j = 0; j < 8; ++j) csum[j][0] = csum[j][1] = 0.f;

#pragma unroll
    for (int i = 0; i < 2; ++i) {
        int r0 = bM + wm + 16 * i + g;
        int r1 = r0 + 8;
        float m0 = g_msn[r0];
        float m1 = g_msn[r1];
#pragma unroll
        for (int j = 0; j < 8; ++j) {
            int c0 = bN + wn + 8 * j + 2 * tg;
            float e0 = tf32r(__expf(m0 * (acc[i][j][0] - bsqv[j][0])));
            float e1 = tf32r(__expf(m0 * (acc[i][j][1] - bsqv[j][1])));
            float e2 = tf32r(__expf(m1 * (acc[i][j][2] - bsqv[j][0])));
            float e3 = tf32r(__expf(m1 * (acc[i][j][3] - bsqv[j][1])));
            *(float2*)&g_S[(size_t)r0 * NP + c0] = make_float2(e0, e1);
            *(float2*)&g_S[(size_t)r1 * NP + c0] = make_float2(e2, e3);
            csum[j][0] += e0 + e2;
            csum[j][1] += e1 + e3;
        }
    }
    // reduce over the 8 row-groups (g) within each warp via shuffle (lane = g*4+tg)
#pragma unroll
    for (int j = 0; j < 8; ++j)
#pragma unroll
        for (int d = 0; d < 2; ++d) {
            float s = csum[j][d];
            s += __shfl_xor_sync(0xffffffffu, s, 4);
            s += __shfl_xor_sync(0xffffffffu, s, 8);
            s += __shfl_xor_sync(0xffffffffu, s, 16);
            if (g == 0) colpart[mw][wn + 8 * j + 2 * tg + d] = s;
        }
    __syncthreads();
    if (tid < 128) {
        float t = colpart[0][tid] + colpart[1][tid] + colpart[2][tid] + colpart[3][tid];
        g_part[(size_t)blockIdx.x * NP + bN + tid] = t;
    }
}

// ---------------- rinv: 1 / sum of the 64 tile partials per pixel ----------------
__global__ void rinv_kernel() {
    int p = blockIdx.x * blockDim.x + threadIdx.x;
    float s = 0.f;
#pragma unroll
    for (int b = 0; b < NBLK; ++b) s += g_part[(size_t)b * NP + p];
    g_rinv[p] = 1.0f / s;
}

// ---------------- readout GEMM: out[v][p] = rinv[p] * sum_n MV[v][n] * E[n][p] -----
#define CBM 128
#define CBN 128
#define CBK 16
#define CKT (NN / CBK)

__global__ __launch_bounds__(256) void out_gemm_kernel(float* __restrict__ out) {
    __shared__ float As[2][CBM][20];
    __shared__ float Bs[2][CBK][136];
    const int tid  = threadIdx.x;
    const int bM   = blockIdx.x * CBM;  // value-dim offset (x fastest -> share E via L2)
    const int bN   = blockIdx.y * CBN;  // pixel offset
    const int warp = tid >> 5;
    const int lane = tid & 31;
    const int wm = (warp & 3) * 32;
    const int wn = (warp >> 2) * 64;
    const int g  = lane >> 2;
    const int tg = lane & 3;

    float acc[2][8][4];
#pragma unroll
    for (int i = 0; i < 2; ++i)
#pragma unroll
        for (int j = 0; j < 8; ++j)
#pragma unroll
            for (int r = 0; r < 4; ++r) acc[i][j][r] = 0.f;

    auto load_tiles = [&](int kt, int stage) {
#pragma unroll
        for (int s = 0; s < 2; ++s) {
            int id = tid + s * 256;
            int r  = id >> 2;
            int c4 = (id & 3) << 2;
            const float* src = &g_MV[(size_t)(bM + r) * NN + kt * CBK + c4];
            cp16((uint32_t)__cvta_generic_to_shared(&As[stage][r][c4]), src);
        }
#pragma unroll
        for (int s = 0; s < 2; ++s) {
            int id = tid + s * 256;
            int r  = id >> 5;
            int c4 = (id & 31) << 2;
            const float* src = &g_S[(size_t)(kt * CBK + r) * NP + bN + c4];
            cp16((uint32_t)__cvta_generic_to_shared(&Bs[stage][r][c4]), src);
        }
    };

    load_tiles(0, 0);
    asm volatile("cp.async.commit_group;\n" ::);

    for (int kt = 0; kt < CKT; ++kt) {
        const int cur = kt & 1;
        if (kt + 1 < CKT) {
            load_tiles(kt + 1, cur ^ 1);
            asm volatile("cp.async.commit_group;\n" ::);
            asm volatile("cp.async.wait_group 1;\n" ::);
        } else {
            asm volatile("cp.async.wait_group 0;\n" ::);
        }
        __syncthreads();

#pragma unroll
        for (int ks = 0; ks < 2; ++ks) {
            const int k0 = ks * 8;
            float af[2][4];
#pragma unroll
            for (int i = 0; i < 2; ++i) {
                int mr = wm + 16 * i;
                af[i][0] = As[cur][mr + g][k0 + tg];
                af[i][1] = As[cur][mr + g + 8][k0 + tg];
                af[i][2] = As[cur][mr + g][k0 + tg + 4];
                af[i][3] = As[cur][mr + g + 8][k0 + tg + 4];
            }
            float bf[8][2];
#pragma unroll
            for (int j = 0; j < 8; ++j) {
                int nc = wn + 8 * j + g;
                bf[j][0] = Bs[cur][k0 + tg][nc];
                bf[j][1] = Bs[cur][k0 + tg + 4][nc];
            }
#pragma unroll
            for (int i = 0; i < 2; ++i)
#pragma unroll
                for (int j = 0; j < 8; ++j)
                    MMA_TF32(acc[i][j], af[i], bf[j]);
        }
        __syncthreads();
    }

#pragma unroll
    for (int j = 0; j < 8; ++j) {
        int c = bN + wn + 8 * j + 2 * tg;
        float r0 = g_rinv[c];
        float r1 = g_rinv[c + 1];
#pragma unroll
        for (int i = 0; i < 2; ++i) {
            int rr = bM + wm + 16 * i + g;
            *(float2*)&out[(size_t)rr * NP + c] =
                make_float2(acc[i][j][0] * r0, acc[i][j][1] * r1);
            *(float2*)&out[(size_t)(rr + 8) * NP + c] =
                make_float2(acc[i][j][2] * r0, acc[i][j][3] * r1);
        }
    }
}

// ---------------- launch ----------------
extern "C" void kernel_launch(void* const* d_in, const int* in_sizes, int n_in,
                              void* d_out, int out_size) {
    const float* qk = (const float*)d_in[0];
    const float* qe = (const float*)d_in[1];
    const float* mk = (const float*)d_in[2];
    const float* ms = (const float*)d_in[3];
    const float* mv = (const float*)d_in[4];
    float* out = (float*)d_out;

    static bool attr_set = false;
    const int SIM_SMEM = (2 * 128 * 20 * 2 + 2 * 16 * 136 * 2) * 4;  // 75776 B
    if (!attr_set) {
        cudaFuncSetAttribute(sim_kernel, cudaFuncAttributeMaxDynamicSharedMemorySize,
                             SIM_SMEM);
        attr_set = true;
    }

    prep_q_kernel<<<NP / 256, 256>>>(qk, qe);
    prep_m_kernel<<<NN / 256, 256>>>(mk, ms);
    prep_mv_kernel<<<(NV * NN / 4) / 256, 256>>>(mv);
    sim_kernel<<<dim3(NN / 128, NP / 128), 256, SIM_SMEM>>>();
    rinv_kernel<<<NP / 256, 256>>>();
    out_gemm_kernel<<<dim3(NV / CBM, NP / CBN), 256>>>(out);
}